// round 4
// baseline (speedup 1.0000x reference)
#include <cuda_runtime.h>
#include <cuda_bf16.h>

// Problem constants (fixed by setup_inputs)
#define CH    16
#define HH    512
#define WW    512
#define KS    7
#define RAD   3
#define DIL   2
#define PAD   6            // RAD*DIL
#define DYN   3            // output channels

// Tiling: 32 x 12 pixels per block, 192 threads, 2 pixels per thread
#define TW    32
#define TPH   12
#define LW    (TW + 2*PAD)   // 44
#define LH    (TPH + 2*PAD)  // 24
#define PLANE (LW*LH)        // 1056
#define NTHREADS 192
#define NPAIR 9              // 9 u64 planes: (c0,c1)(c2,ONE)(c3,S2)(c4,c5)...(c14,c15)

#define SMEM_BYTES (NPAIR * PLANE * 8)   // 76032 B -> 3 blocks/SM

#define LOG2E 1.4426950408889634f

typedef unsigned long long u64;

__device__ __forceinline__ u64 pk2(float lo, float hi) {
    u64 r; asm("mov.b64 %0,{%1,%2};" : "=l"(r) : "f"(lo), "f"(hi)); return r;
}
__device__ __forceinline__ void upk2(u64 v, float& lo, float& hi) {
    asm("mov.b64 {%0,%1},%2;" : "=f"(lo), "=f"(hi) : "l"(v));
}
__device__ __forceinline__ u64 ffma2(u64 a, u64 b, u64 c) {
    u64 d; asm("fma.rn.f32x2 %0,%1,%2,%3;" : "=l"(d) : "l"(a), "l"(b), "l"(c)); return d;
}
__device__ __forceinline__ u64 fadd2(u64 a, u64 b) {
    u64 d; asm("add.rn.f32x2 %0,%1,%2;" : "=l"(d) : "l"(a), "l"(b)); return d;
}
__device__ __forceinline__ u64 fmul2(u64 a, u64 b) {
    u64 d; asm("mul.rn.f32x2 %0,%1,%2;" : "=l"(d) : "l"(a), "l"(b)); return d;
}
__device__ __forceinline__ float ex2(float x) {
    float r; asm("ex2.approx.f32 %0,%1;" : "=f"(r) : "f"(x)); return r;
}

// channel -> (pair, half) slot map
// slots: p0=(c0,c1) p1=(c2,ONE) p2=(c3,S2) p3=(c4,c5) ... p8=(c14,c15)
__device__ __constant__ int KMAP[16] = {0,0,1,2,3,3,4,4,5,5,6,6,7,7,8,8};
__device__ __constant__ int HMAP[16] = {0,1,0,0,0,1,0,1,0,1,0,1,0,1,0,1};

__global__ __launch_bounds__(NTHREADS, 3)
void bilateral_kernel(const float* __restrict__ in,
                      const float* __restrict__ prm,
                      float* __restrict__ out)
{
    extern __shared__ float smf[];
    u64* tile = (u64*)smf;               // [NPAIR][PLANE]

    const int tx  = threadIdx.x;         // 0..31
    const int ty  = threadIdx.y;         // 0..5
    const int tid = ty * TW + tx;
    const int bx0 = blockIdx.x * TW;
    const int by0 = blockIdx.y * TPH;
    const int b   = blockIdx.z;

    float rcl[CH];                       // rc * log2e
    #pragma unroll
    for (int c = 0; c < CH; c++) rcl[c] = __ldg(&prm[c]) * LOG2E;
    const float sxl = __ldg(&prm[CH]) * LOG2E;
    const float syl = __ldg(&prm[CH + 1]) * LOG2E;

    const float* inb = in + (size_t)b * CH * HH * WW;

    // ---- Phase 1: load haloed tile into paired slots (zero-fill OOB), fill ONE ----
    #pragma unroll 1
    for (int c = 0; c < CH; c++) {
        const int slot0 = KMAP[c] * 2 * PLANE + HMAP[c];
        const float* src = inb + (size_t)c * HH * WW;
        for (int p = tid; p < PLANE; p += NTHREADS) {
            int lr = p / LW;
            int lc = p - lr * LW;
            int gy = by0 + lr - PAD;
            int gx = bx0 + lc - PAD;
            float v = 0.0f;
            if ((unsigned)gy < (unsigned)HH && (unsigned)gx < (unsigned)WW)
                v = __ldg(&src[(size_t)gy * WW + gx]);
            smf[slot0 + 2 * p] = v;
        }
    }
    for (int p = tid; p < PLANE; p += NTHREADS)
        smf[1 * 2 * PLANE + 2 * p + 1] = 1.0f;     // ONE slot (p1 hi)
    __syncthreads();

    // ---- Phase 2: s2'(q) = log2e * sum_c rc_c x_c(q)^2 into p2-hi ; -1e30 if OOB ----
    {
        // packed coefficients for pairs p0, p3..p8 (p1/p2 handled scalar, lo only)
        u64 rcp0 = pk2(rcl[0], rcl[1]);
        u64 rcp[6];
        #pragma unroll
        for (int k = 0; k < 6; k++) rcp[k] = pk2(rcl[4 + 2*k], rcl[5 + 2*k]);

        for (int p = tid; p < PLANE; p += NTHREADS) {
            int lr = p / LW;
            int lc = p - lr * LW;
            int gy = by0 + lr - PAD;
            int gx = bx0 + lc - PAD;
            float s = -1e30f;
            if ((unsigned)gy < (unsigned)HH && (unsigned)gx < (unsigned)WW) {
                u64 x0 = tile[0 * PLANE + p];
                u64 A  = fmul2(fmul2(rcp0, x0), x0);
                #pragma unroll
                for (int k = 0; k < 6; k++) {
                    u64 x = tile[(3 + k) * PLANE + p];
                    A = ffma2(fmul2(rcp[k], x), x, A);
                }
                float alo, ahi;
                upk2(A, alo, ahi);
                float c2 = smf[1 * 2 * PLANE + 2 * p];   // p1 lo
                float c3 = smf[2 * 2 * PLANE + 2 * p];   // p2 lo
                s = (alo + ahi) + (fmaf(rcl[2] * c2, c2, rcl[3] * c3 * c3));
            }
            smf[2 * 2 * PLANE + 2 * p + 1] = s;          // S2 slot (p2 hi)
        }
    }
    __syncthreads();

    // ---- Phase 3: two pixels per thread (rows lr0, lr0+2 share tap rows) ----
    const int lr0 = 4 * (ty >> 1) + (ty & 1);   // ty 0..5 -> rows {0,2},{1,3},{4,6},{5,7},{8,10},{9,11}
    const int cp0 = (lr0 + PAD) * LW + (tx + PAD);
    const int cp1 = cp0 + 2 * LW;

    // y vectors per pixel: y_k = (-2*rc') .* x_center, with
    //   p1: (y_c2, 0)    -> ONE contributes 0 to dot
    //   p2: (y_c3, 1.0)  -> S2(q) flows through the chain
    u64 rcn2[NPAIR];
    rcn2[0] = pk2(-2.0f * rcl[0], -2.0f * rcl[1]);
    rcn2[1] = pk2(-2.0f * rcl[2], 0.0f);
    rcn2[2] = pk2(-2.0f * rcl[3], 0.0f);
    #pragma unroll
    for (int k = 3; k < NPAIR; k++)
        rcn2[k] = pk2(-2.0f * rcl[2*k - 2], -2.0f * rcl[2*k - 1]);

    u64 y0p[NPAIR], y1p[NPAIR];
    float s2p0, s2p1;
    #pragma unroll
    for (int k = 0; k < NPAIR; k++) {
        u64 xc0 = tile[k * PLANE + cp0];
        u64 xc1 = tile[k * PLANE + cp1];
        y0p[k] = fmul2(rcn2[k], xc0);
        y1p[k] = fmul2(rcn2[k], xc1);
        if (k == 2) {
            float lo, hi;
            upk2(xc0, lo, s2p0);                 // center s2' for pixel0
            upk2(xc1, lo, s2p1);                 // center s2' for pixel1
            upk2(y0p[2], lo, hi); y0p[2] = pk2(lo, 1.0f);
            upk2(y1p[2], lo, hi); y1p[2] = pk2(lo, 1.0f);
        }
    }

    float sxj[KS];
    #pragma unroll
    for (int j = 0; j < KS; j++) {
        float dxf = (float)((j - RAD) * DIL);
        sxj[j] = sxl * dxf * dxf;
    }

    u64 N01_0 = 0ull, N2D_0 = 0ull;   // (num0,num1), (num2,den) pixel0
    u64 N01_1 = 0ull, N2D_1 = 0ull;   // pixel1

    // Tap rows (padded coords): lr0 + 2*i, i = 0..7.
    // i in [0,6] valid for pixel0 (dy0 = 2i-6); i in [1,7] valid for pixel1 (dy1 = 2i-8).
    #pragma unroll 1
    for (int i = 0; i < 8; i++) {
        const float dy0 = (float)(2 * i - 6);
        const float dy1 = (float)(2 * i - 8);
        float base0 = fmaf(syl * dy0, dy0, s2p0);
        float base1 = fmaf(syl * dy1, dy1, s2p1);
        if (i == 7) base0 = -3e30f;   // row invalid for pixel0 -> w=0
        if (i == 0) base1 = -3e30f;   // row invalid for pixel1 -> w=0
        const int rowoff = (lr0 + 2 * i) * LW + tx;

        #pragma unroll
        for (int j = 0; j < KS; j++) {
            const int p = rowoff + 2 * j;
            const float tb0 = base0 + sxj[j];
            const float tb1 = base1 + sxj[j];

            u64 xp[NPAIR];
            #pragma unroll
            for (int k = 0; k < NPAIR; k++) xp[k] = tile[k * PLANE + p];

            // Packed dot products (include s2q via p2-hi); 2 chains per pixel
            u64 A0 = fmul2(y0p[0], xp[0]);
            u64 A1 = fmul2(y0p[1], xp[1]);
            u64 B0 = fmul2(y1p[0], xp[0]);
            u64 B1 = fmul2(y1p[1], xp[1]);
            #pragma unroll
            for (int k = 2; k < NPAIR; k += 2) {
                A0 = ffma2(y0p[k], xp[k], A0);
                B0 = ffma2(y1p[k], xp[k], B0);
            }
            #pragma unroll
            for (int k = 3; k < NPAIR; k += 2) {
                A1 = ffma2(y0p[k], xp[k], A1);
                B1 = ffma2(y1p[k], xp[k], B1);
            }
            u64 SA = fadd2(A0, A1);
            u64 SB = fadd2(B0, B1);
            float salo, sahi, sblo, sbhi;
            upk2(SA, salo, sahi);
            upk2(SB, sblo, sbhi);

            const float w0 = ex2((salo + sahi) + tb0);
            const float w1 = ex2((sblo + sbhi) + tb1);

            const u64 wpk0 = pk2(w0, w0);
            const u64 wpk1 = pk2(w1, w1);
            N01_0 = ffma2(wpk0, xp[0], N01_0);   // += (w*c0, w*c1)
            N2D_0 = ffma2(wpk0, xp[1], N2D_0);   // += (w*c2, w*1.0)
            N01_1 = ffma2(wpk1, xp[0], N01_1);
            N2D_1 = ffma2(wpk1, xp[1], N2D_1);
        }
    }

    float n00, n01, n02, d0, n10, n11, n12, d1;
    upk2(N01_0, n00, n01);
    upk2(N2D_0, n02, d0);
    upk2(N01_1, n10, n11);
    upk2(N2D_1, n12, d1);

    const float inv0 = __fdividef(1.0f, d0);   // den >= 1 for valid pixels
    const float inv1 = __fdividef(1.0f, d1);
    const int gy0 = by0 + lr0;
    const int gy1 = gy0 + 2;
    const int gx  = bx0 + tx;
    const size_t CS = (size_t)HH * WW;
    const size_t ob = (size_t)b * DYN * CS + gx;
    if (gy0 < HH) {
        size_t o0 = ob + (size_t)gy0 * WW;
        out[o0]          = n00 * inv0;
        out[o0 + CS]     = n01 * inv0;
        out[o0 + 2 * CS] = n02 * inv0;
    }
    if (gy1 < HH) {
        size_t o1 = ob + (size_t)gy1 * WW;
        out[o1]          = n10 * inv1;
        out[o1 + CS]     = n11 * inv1;
        out[o1 + 2 * CS] = n12 * inv1;
    }
}

extern "C" void kernel_launch(void* const* d_in, const int* in_sizes, int n_in,
                              void* d_out, int out_size)
{
    const float* in  = (const float*)d_in[0];
    const float* prm = (const float*)d_in[1];
    float*       out = (float*)d_out;

    const int B = in_sizes[0] / (CH * HH * WW);   // = 4

    cudaFuncSetAttribute(bilateral_kernel,
                         cudaFuncAttributeMaxDynamicSharedMemorySize,
                         (int)SMEM_BYTES);

    dim3 block(TW, 6, 1);                              // 192 threads
    dim3 grid(WW / TW, (HH + TPH - 1) / TPH, B);       // 16 x 43 x 4
    bilateral_kernel<<<grid, block, SMEM_BYTES>>>(in, prm, out);
}

// round 5
// speedup vs baseline: 1.0639x; 1.0639x over previous
#include <cuda_runtime.h>
#include <cuda_bf16.h>

// Problem constants (fixed by setup_inputs)
#define CH    16
#define HH    512
#define WW    512
#define KS    7
#define RAD   3
#define DIL   2
#define PAD   6            // RAD*DIL
#define DYN   3            // output channels

// Tiling: 32 x 16 pixels per block, 256 threads, 2 pixels per thread
#define TW    32
#define TPH   16
#define LW    (TW + 2*PAD)   // 44
#define LH    (TPH + 2*PAD)  // 28
#define PLANE (LW*LH)        // 1232
#define NTHREADS 256
#define NPAIR 9              // u64 planes: (c0,c1)(c2,ONE)(c3,S2)(c4,c5)...(c14,c15)

#define SMEM_BYTES (NPAIR * PLANE * 8)   // 88704 B -> 2 blocks/SM

#define LOG2E 1.4426950408889634f

typedef unsigned long long u64;

__device__ __forceinline__ u64 pk2(float lo, float hi) {
    u64 r; asm("mov.b64 %0,{%1,%2};" : "=l"(r) : "f"(lo), "f"(hi)); return r;
}
__device__ __forceinline__ void upk2(u64 v, float& lo, float& hi) {
    asm("mov.b64 {%0,%1},%2;" : "=f"(lo), "=f"(hi) : "l"(v));
}
__device__ __forceinline__ u64 ffma2(u64 a, u64 b, u64 c) {
    u64 d; asm("fma.rn.f32x2 %0,%1,%2,%3;" : "=l"(d) : "l"(a), "l"(b), "l"(c)); return d;
}
__device__ __forceinline__ u64 fadd2(u64 a, u64 b) {
    u64 d; asm("add.rn.f32x2 %0,%1,%2;" : "=l"(d) : "l"(a), "l"(b)); return d;
}
__device__ __forceinline__ u64 fmul2(u64 a, u64 b) {
    u64 d; asm("mul.rn.f32x2 %0,%1,%2;" : "=l"(d) : "l"(a), "l"(b)); return d;
}
__device__ __forceinline__ float ex2(float x) {
    float r; asm("ex2.approx.f32 %0,%1;" : "=f"(r) : "f"(x)); return r;
}

// channel -> (pair, half) slot map
// slots: p0=(c0,c1) p1=(c2,ONE) p2=(c3,S2) p3=(c4,c5) ... p8=(c14,c15)
__device__ __constant__ int KMAP[16] = {0,0,1,2,3,3,4,4,5,5,6,6,7,7,8,8};
__device__ __constant__ int HMAP[16] = {0,1,0,0,0,1,0,1,0,1,0,1,0,1,0,1};

__global__ __launch_bounds__(NTHREADS, 2)
void bilateral_kernel(const float* __restrict__ in,
                      const float* __restrict__ prm,
                      float* __restrict__ out)
{
    extern __shared__ float smf[];
    u64* tile = (u64*)smf;               // [NPAIR][PLANE]

    const int tx  = threadIdx.x;         // 0..31
    const int ty  = threadIdx.y;         // 0..7
    const int tid = ty * TW + tx;
    const int bx0 = blockIdx.x * TW;
    const int by0 = blockIdx.y * TPH;
    const int b   = blockIdx.z;

    float rcl[CH];                       // rc * log2e
    #pragma unroll
    for (int c = 0; c < CH; c++) rcl[c] = __ldg(&prm[c]) * LOG2E;
    const float sxl = __ldg(&prm[CH]) * LOG2E;
    const float syl = __ldg(&prm[CH + 1]) * LOG2E;

    const float* inb = in + (size_t)b * CH * HH * WW;

    // ---- Phase 1: load haloed tile into paired slots (zero-fill OOB), fill ONE ----
    #pragma unroll 1
    for (int c = 0; c < CH; c++) {
        const int slot0 = KMAP[c] * 2 * PLANE + HMAP[c];
        const float* src = inb + (size_t)c * HH * WW;
        for (int p = tid; p < PLANE; p += NTHREADS) {
            int lr = p / LW;
            int lc = p - lr * LW;
            int gy = by0 + lr - PAD;
            int gx = bx0 + lc - PAD;
            float v = 0.0f;
            if ((unsigned)gy < (unsigned)HH && (unsigned)gx < (unsigned)WW)
                v = __ldg(&src[(size_t)gy * WW + gx]);
            smf[slot0 + 2 * p] = v;
        }
    }
    for (int p = tid; p < PLANE; p += NTHREADS)
        smf[1 * 2 * PLANE + 2 * p + 1] = 1.0f;     // ONE slot (p1 hi)
    __syncthreads();

    // ---- Phase 2: s2'(q) = log2e * sum_c rc_c x_c(q)^2 into p2-hi ; -1e30 if OOB ----
    {
        u64 rcp0 = pk2(rcl[0], rcl[1]);
        u64 rcp[6];
        #pragma unroll
        for (int k = 0; k < 6; k++) rcp[k] = pk2(rcl[4 + 2*k], rcl[5 + 2*k]);

        for (int p = tid; p < PLANE; p += NTHREADS) {
            int lr = p / LW;
            int lc = p - lr * LW;
            int gy = by0 + lr - PAD;
            int gx = bx0 + lc - PAD;
            float s = -1e30f;
            if ((unsigned)gy < (unsigned)HH && (unsigned)gx < (unsigned)WW) {
                u64 x0 = tile[0 * PLANE + p];
                u64 A  = fmul2(fmul2(rcp0, x0), x0);
                #pragma unroll
                for (int k = 0; k < 6; k++) {
                    u64 x = tile[(3 + k) * PLANE + p];
                    A = ffma2(fmul2(rcp[k], x), x, A);
                }
                float alo, ahi;
                upk2(A, alo, ahi);
                float c2 = smf[1 * 2 * PLANE + 2 * p];   // p1 lo
                float c3 = smf[2 * 2 * PLANE + 2 * p];   // p2 lo
                s = (alo + ahi) + (fmaf(rcl[2] * c2, c2, rcl[3] * c3 * c3));
            }
            smf[2 * 2 * PLANE + 2 * p + 1] = s;          // S2 slot (p2 hi)
        }
    }
    __syncthreads();

    // ---- Phase 3: two pixels per thread (rows lr0, lr0+2 share tap rows) ----
    const int lr0 = 4 * (ty >> 1) + (ty & 1);   // rows {0,2},{1,3},{4,6},{5,7},{8,10},{9,11},{12,14},{13,15}
    const int cp0 = (lr0 + PAD) * LW + (tx + PAD);
    const int cp1 = cp0 + 2 * LW;

    // y vectors per pixel: y_k = (-2*rc') .* x_center, with
    //   p1: (y_c2, 0)    -> ONE contributes 0 to dot
    //   p2: (y_c3, 1.0)  -> S2(q) flows through the chain
    u64 rcn2[NPAIR];
    rcn2[0] = pk2(-2.0f * rcl[0], -2.0f * rcl[1]);
    rcn2[1] = pk2(-2.0f * rcl[2], 0.0f);
    rcn2[2] = pk2(-2.0f * rcl[3], 0.0f);
    #pragma unroll
    for (int k = 3; k < NPAIR; k++)
        rcn2[k] = pk2(-2.0f * rcl[2*k - 2], -2.0f * rcl[2*k - 1]);

    u64 y0p[NPAIR], y1p[NPAIR];
    float s2p0, s2p1;
    #pragma unroll
    for (int k = 0; k < NPAIR; k++) {
        u64 xc0 = tile[k * PLANE + cp0];
        u64 xc1 = tile[k * PLANE + cp1];
        y0p[k] = fmul2(rcn2[k], xc0);
        y1p[k] = fmul2(rcn2[k], xc1);
        if (k == 2) {
            float lo, hi;
            upk2(xc0, lo, s2p0);                 // center s2' for pixel0
            upk2(xc1, lo, s2p1);                 // center s2' for pixel1
            upk2(y0p[2], lo, hi); y0p[2] = pk2(lo, 1.0f);
            upk2(y1p[2], lo, hi); y1p[2] = pk2(lo, 1.0f);
        }
    }

    float sxj[KS];
    #pragma unroll
    for (int j = 0; j < KS; j++) {
        float dxf = (float)((j - RAD) * DIL);
        sxj[j] = sxl * dxf * dxf;
    }

    u64 N01_0 = 0ull, N2D_0 = 0ull;   // (num0,num1), (num2,den) pixel0
    u64 N01_1 = 0ull, N2D_1 = 0ull;   // pixel1

    // Tap rows (padded coords): lr0 + 2*i, i = 0..7.
    // i in [0,6] valid for pixel0 (dy0 = 2i-6); i in [1,7] valid for pixel1 (dy1 = 2i-8).
    #pragma unroll 1
    for (int i = 0; i < 8; i++) {
        const float dy0 = (float)(2 * i - 6);
        const float dy1 = (float)(2 * i - 8);
        float base0 = fmaf(syl * dy0, dy0, s2p0);
        float base1 = fmaf(syl * dy1, dy1, s2p1);
        if (i == 7) base0 = -3e30f;   // row invalid for pixel0 -> w=0
        if (i == 0) base1 = -3e30f;   // row invalid for pixel1 -> w=0
        const int rowoff = (lr0 + 2 * i) * LW + tx;

        #pragma unroll
        for (int j = 0; j < KS; j++) {
            const int p = rowoff + 2 * j;
            const float tb0 = base0 + sxj[j];
            const float tb1 = base1 + sxj[j];

            u64 xp[NPAIR];
            #pragma unroll
            for (int k = 0; k < NPAIR; k++) xp[k] = tile[k * PLANE + p];

            // Packed dot products (include s2q via p2-hi); 2 chains per pixel
            u64 A0 = fmul2(y0p[0], xp[0]);
            u64 A1 = fmul2(y0p[1], xp[1]);
            u64 B0 = fmul2(y1p[0], xp[0]);
            u64 B1 = fmul2(y1p[1], xp[1]);
            #pragma unroll
            for (int k = 2; k < NPAIR; k += 2) {
                A0 = ffma2(y0p[k], xp[k], A0);
                B0 = ffma2(y1p[k], xp[k], B0);
            }
            #pragma unroll
            for (int k = 3; k < NPAIR; k += 2) {
                A1 = ffma2(y0p[k], xp[k], A1);
                B1 = ffma2(y1p[k], xp[k], B1);
            }
            u64 SA = fadd2(A0, A1);
            u64 SB = fadd2(B0, B1);
            float salo, sahi, sblo, sbhi;
            upk2(SA, salo, sahi);
            upk2(SB, sblo, sbhi);

            const float w0 = ex2((salo + sahi) + tb0);
            const float w1 = ex2((sblo + sbhi) + tb1);

            const u64 wpk0 = pk2(w0, w0);
            const u64 wpk1 = pk2(w1, w1);
            N01_0 = ffma2(wpk0, xp[0], N01_0);   // += (w*c0, w*c1)
            N2D_0 = ffma2(wpk0, xp[1], N2D_0);   // += (w*c2, w*1.0)
            N01_1 = ffma2(wpk1, xp[0], N01_1);
            N2D_1 = ffma2(wpk1, xp[1], N2D_1);
        }
    }

    float n00, n01, n02, d0, n10, n11, n12, d1;
    upk2(N01_0, n00, n01);
    upk2(N2D_0, n02, d0);
    upk2(N01_1, n10, n11);
    upk2(N2D_1, n12, d1);

    const float inv0 = __fdividef(1.0f, d0);   // den >= 1 (center tap w=1)
    const float inv1 = __fdividef(1.0f, d1);
    const int gy0 = by0 + lr0;
    const int gy1 = gy0 + 2;
    const int gx  = bx0 + tx;
    const size_t CS = (size_t)HH * WW;
    const size_t ob = (size_t)b * DYN * CS + gx;
    {
        size_t o0 = ob + (size_t)gy0 * WW;
        out[o0]          = n00 * inv0;
        out[o0 + CS]     = n01 * inv0;
        out[o0 + 2 * CS] = n02 * inv0;
    }
    {
        size_t o1 = ob + (size_t)gy1 * WW;
        out[o1]          = n10 * inv1;
        out[o1 + CS]     = n11 * inv1;
        out[o1 + 2 * CS] = n12 * inv1;
    }
}

extern "C" void kernel_launch(void* const* d_in, const int* in_sizes, int n_in,
                              void* d_out, int out_size)
{
    const float* in  = (const float*)d_in[0];
    const float* prm = (const float*)d_in[1];
    float*       out = (float*)d_out;

    const int B = in_sizes[0] / (CH * HH * WW);   // = 4

    cudaFuncSetAttribute(bilateral_kernel,
                         cudaFuncAttributeMaxDynamicSharedMemorySize,
                         (int)SMEM_BYTES);

    dim3 block(TW, 8, 1);                         // 256 threads
    dim3 grid(WW / TW, HH / TPH, B);              // 16 x 32 x 4
    bilateral_kernel<<<grid, block, SMEM_BYTES>>>(in, prm, out);
}

// round 6
// speedup vs baseline: 1.7887x; 1.6814x over previous
#include <cuda_runtime.h>
#include <cuda_bf16.h>

// Problem constants (fixed by setup_inputs)
#define CH    16
#define HH    512
#define WW    512
#define KS    7
#define RAD   3
#define DIL   2
#define PAD   6            // RAD*DIL
#define DYN   3            // output channels

// Tiling: 32 x 16 pixels per block, 256 threads, 2 pixels per thread
#define TW    32
#define TPH   16
#define LW    (TW + 2*PAD)   // 44
#define LH    (TPH + 2*PAD)  // 28
#define PLANE (LW*LH)        // 1232
#define NTHREADS 256
#define NPAIR (CH/2)         // 8 channel pairs

#define SMEM_BYTES ((CH + 1) * PLANE * sizeof(float))   // 83776 B

#define LOG2E 1.4426950408889634f

typedef unsigned long long u64;

__device__ __forceinline__ u64 pk2(float lo, float hi) {
    u64 r; asm("mov.b64 %0,{%1,%2};" : "=l"(r) : "f"(lo), "f"(hi)); return r;
}
__device__ __forceinline__ void upk2(u64 v, float& lo, float& hi) {
    asm("mov.b64 {%0,%1},%2;" : "=f"(lo), "=f"(hi) : "l"(v));
}
__device__ __forceinline__ u64 ffma2(u64 a, u64 b, u64 c) {
    u64 d; asm("fma.rn.f32x2 %0,%1,%2,%3;" : "=l"(d) : "l"(a), "l"(b), "l"(c)); return d;
}
__device__ __forceinline__ u64 fadd2(u64 a, u64 b) {
    u64 d; asm("add.rn.f32x2 %0,%1,%2;" : "=l"(d) : "l"(a), "l"(b)); return d;
}
__device__ __forceinline__ u64 fmul2(u64 a, u64 b) {
    u64 d; asm("mul.rn.f32x2 %0,%1,%2;" : "=l"(d) : "l"(a), "l"(b)); return d;
}
__device__ __forceinline__ float ex2(float x) {
    float r; asm("ex2.approx.f32 %0,%1;" : "=f"(r) : "f"(x)); return r;
}

__global__ __launch_bounds__(NTHREADS, 2)
void bilateral_kernel(const float* __restrict__ in,
                      const float* __restrict__ prm,
                      float* __restrict__ out)
{
    extern __shared__ float sm[];
    // Channel-pair interleaved tile: u64 view [NPAIR][PLANE], pair k holds (ch 2k, 2k+1)
    u64*   tile64 = (u64*)sm;
    float* s2t    = sm + CH * PLANE;     // [LH][LW], -1e30 marks OOB pixels

    const int tx  = threadIdx.x;         // 0..31
    const int ty  = threadIdx.y;         // 0..7
    const int tid = ty * TW + tx;
    const int bx0 = blockIdx.x * TW;
    const int by0 = blockIdx.y * TPH;
    const int b   = blockIdx.z;

    // Coefficients pre-scaled by log2(e): logw computed directly in base-2 -> ex2
    float rcl[CH];
    #pragma unroll
    for (int c = 0; c < CH; c++) rcl[c] = __ldg(&prm[c]) * LOG2E;
    const float sxl = __ldg(&prm[CH]) * LOG2E;
    const float syl = __ldg(&prm[CH + 1]) * LOG2E;

    const float* inb = in + (size_t)b * CH * HH * WW;

    // ---- Phase 1: load haloed tile into pair-interleaved smem (zero-fill OOB) ----
    for (int idx = tid; idx < CH * PLANE; idx += NTHREADS) {
        int pair = idx / (2 * PLANE);
        int rem  = idx - pair * (2 * PLANE);
        int p    = rem >> 1;
        int c    = 2 * pair + (rem & 1);
        int lr = p / LW;
        int lc = p - lr * LW;
        int gy = by0 + lr - PAD;
        int gx = bx0 + lc - PAD;
        float v = 0.0f;
        if ((unsigned)gy < (unsigned)HH && (unsigned)gx < (unsigned)WW)
            v = __ldg(&inb[(size_t)c * HH * WW + (size_t)gy * WW + gx]);
        sm[idx] = v;
    }
    __syncthreads();

    // ---- Phase 2: s2'(q) = log2e * sum_c rc_c * x_c(q)^2 ; -1e30 where OOB ----
    for (int p = tid; p < PLANE; p += NTHREADS) {
        int lr = p / LW;
        int lc = p - lr * LW;
        int gy = by0 + lr - PAD;
        int gx = bx0 + lc - PAD;
        float s = -1e30f;
        if ((unsigned)gy < (unsigned)HH && (unsigned)gx < (unsigned)WW) {
            float a0 = 0.f, a1 = 0.f, a2 = 0.f, a3 = 0.f;
            #pragma unroll
            for (int k = 0; k < NPAIR; k += 2) {
                float xl0, xh0, xl1, xh1;
                upk2(tile64[(k + 0) * PLANE + p], xl0, xh0);
                upk2(tile64[(k + 1) * PLANE + p], xl1, xh1);
                a0 = fmaf(rcl[2*k + 0] * xl0, xl0, a0);
                a1 = fmaf(rcl[2*k + 1] * xh0, xh0, a1);
                a2 = fmaf(rcl[2*k + 2] * xl1, xl1, a2);
                a3 = fmaf(rcl[2*k + 3] * xh1, xh1, a3);
            }
            s = (a0 + a1) + (a2 + a3);
        }
        s2t[p] = s;
    }
    __syncthreads();

    // ---- Phase 3: two pixels per thread (rows lr0, lr0+2 share tap rows) ----
    const int lr0 = 4 * (ty >> 1) + (ty & 1);
    const int cp0 = (lr0 + PAD) * LW + (tx + PAD);
    const int cp1 = cp0 + 2 * LW;

    // Packed y vectors: y_pair = (-2*rc') .* x_center  (per pair)
    u64 rcn2[NPAIR];
    #pragma unroll
    for (int k = 0; k < NPAIR; k++)
        rcn2[k] = pk2(-2.0f * rcl[2*k], -2.0f * rcl[2*k + 1]);

    u64 y0p[NPAIR], y1p[NPAIR];
    #pragma unroll
    for (int k = 0; k < NPAIR; k++) {
        y0p[k] = fmul2(rcn2[k], tile64[k * PLANE + cp0]);
        y1p[k] = fmul2(rcn2[k], tile64[k * PLANE + cp1]);
    }
    const float s2p0 = s2t[cp0];
    const float s2p1 = s2t[cp1];

    float sxj[KS];
    #pragma unroll
    for (int j = 0; j < KS; j++) {
        float dxf = (float)((j - RAD) * DIL);
        sxj[j] = sxl * dxf * dxf;
    }

    float n00 = 0.f, n01 = 0.f, n02 = 0.f, d0 = 0.f;
    float n10 = 0.f, n11 = 0.f, n12 = 0.f, d1 = 0.f;

    // Tap rows (padded coords): lr0 + 2*i, i = 0..7.
    // i in [0,6] valid for pixel0 (dy0 = 2i-6); i in [1,7] valid for pixel1 (dy1 = 2i-8).
    #pragma unroll 1
    for (int i = 0; i < 8; i++) {
        const float dy0 = (float)(2 * i - 6);
        const float dy1 = (float)(2 * i - 8);
        float base0 = fmaf(syl * dy0, dy0, s2p0);
        float base1 = fmaf(syl * dy1, dy1, s2p1);
        if (i == 7) base0 = -3e30f;   // row invalid for pixel0 -> w=0
        if (i == 0) base1 = -3e30f;   // row invalid for pixel1 -> w=0
        const int rowoff = (lr0 + 2 * i) * LW + tx;

        #pragma unroll
        for (int j = 0; j < KS; j++) {
            const int p = rowoff + 2 * j;
            const float t   = s2t[p] + sxj[j];
            const float tb0 = t + base0;
            const float tb1 = t + base1;

            u64 xp[NPAIR];
            #pragma unroll
            for (int k = 0; k < NPAIR; k++) xp[k] = tile64[k * PLANE + p];

            // Two packed chains of depth 4 per pixel
            u64 A0 = fmul2(y0p[0], xp[0]);
            u64 A1 = fmul2(y0p[1], xp[1]);
            u64 B0 = fmul2(y1p[0], xp[0]);
            u64 B1 = fmul2(y1p[1], xp[1]);
            #pragma unroll
            for (int k = 2; k < NPAIR; k += 2) {
                A0 = ffma2(y0p[k],     xp[k],     A0);
                A1 = ffma2(y0p[k + 1], xp[k + 1], A1);
                B0 = ffma2(y1p[k],     xp[k],     B0);
                B1 = ffma2(y1p[k + 1], xp[k + 1], B1);
            }
            u64 SA = fadd2(A0, A1);
            u64 SB = fadd2(B0, B1);
            float salo, sahi, sblo, sbhi;
            upk2(SA, salo, sahi);
            upk2(SB, sblo, sbhi);

            const float w0 = ex2((salo + sahi) + tb0);   // base-2, coeffs prescaled
            const float w1 = ex2((sblo + sbhi) + tb1);

            float x0, x1, x2, x3dummy;
            upk2(xp[0], x0, x1);
            upk2(xp[1], x2, x3dummy);

            n00 = fmaf(w0, x0, n00);
            n01 = fmaf(w0, x1, n01);
            n02 = fmaf(w0, x2, n02);
            d0 += w0;
            n10 = fmaf(w1, x0, n10);
            n11 = fmaf(w1, x1, n11);
            n12 = fmaf(w1, x2, n12);
            d1 += w1;
        }
    }

    const float inv0 = __fdividef(1.0f, d0);   // den >= 1 (center tap w=1)
    const float inv1 = __fdividef(1.0f, d1);
    const int gy0 = by0 + lr0;
    const int gx  = bx0 + tx;
    size_t o0 = (size_t)b * DYN * HH * WW + (size_t)gy0 * WW + gx;
    size_t o1 = o0 + 2 * (size_t)WW;
    const size_t CS = (size_t)HH * WW;
    out[o0]          = n00 * inv0;
    out[o0 + CS]     = n01 * inv0;
    out[o0 + 2 * CS] = n02 * inv0;
    out[o1]          = n10 * inv1;
    out[o1 + CS]     = n11 * inv1;
    out[o1 + 2 * CS] = n12 * inv1;
}

extern "C" void kernel_launch(void* const* d_in, const int* in_sizes, int n_in,
                              void* d_out, int out_size)
{
    const float* in  = (const float*)d_in[0];
    const float* prm = (const float*)d_in[1];
    float*       out = (float*)d_out;

    const int B = in_sizes[0] / (CH * HH * WW);   // = 4

    cudaFuncSetAttribute(bilateral_kernel,
                         cudaFuncAttributeMaxDynamicSharedMemorySize,
                         (int)SMEM_BYTES);

    dim3 block(TW, 8, 1);                         // 256 threads
    dim3 grid(WW / TW, HH / TPH, B);              // 16 x 32 x 4
    bilateral_kernel<<<grid, block, SMEM_BYTES>>>(in, prm, out);
}

// round 7
// speedup vs baseline: 1.8152x; 1.0148x over previous
#include <cuda_runtime.h>
#include <cuda_bf16.h>

// Problem constants (fixed by setup_inputs)
#define CH    16
#define HH    512
#define WW    512
#define KS    7
#define RAD   3
#define DIL   2
#define PAD   6            // RAD*DIL
#define DYN   3            // output channels

// Tiling: 32 x 24 pixels per block, 256 threads, 3 pixels per thread
#define TW    32
#define TPH   24
#define LW    (TW + 2*PAD)   // 44
#define LH    (TPH + 2*PAD)  // 36
#define PLANE (LW*LH)        // 1584
#define NTHREADS 256
#define NPAIR 8              // channel pairs
#define NQUAD 4              // channel quads

#define SMEM_BYTES (17 * PLANE * 4)   // 16 channel planes + s2 plane = 107712 B

#define LOG2E 1.4426950408889634f

typedef unsigned long long u64;

__device__ __forceinline__ u64 pk2(float lo, float hi) {
    u64 r; asm("mov.b64 %0,{%1,%2};" : "=l"(r) : "f"(lo), "f"(hi)); return r;
}
__device__ __forceinline__ void upk2(u64 v, float& lo, float& hi) {
    asm("mov.b64 {%0,%1},%2;" : "=f"(lo), "=f"(hi) : "l"(v));
}
__device__ __forceinline__ u64 ffma2(u64 a, u64 b, u64 c) {
    u64 d; asm("fma.rn.f32x2 %0,%1,%2,%3;" : "=l"(d) : "l"(a), "l"(b), "l"(c)); return d;
}
__device__ __forceinline__ u64 fadd2(u64 a, u64 b) {
    u64 d; asm("add.rn.f32x2 %0,%1,%2;" : "=l"(d) : "l"(a), "l"(b)); return d;
}
__device__ __forceinline__ u64 fmul2(u64 a, u64 b) {
    u64 d; asm("mul.rn.f32x2 %0,%1,%2;" : "=l"(d) : "l"(a), "l"(b)); return d;
}
__device__ __forceinline__ float ex2(float x) {
    float r; asm("ex2.approx.f32 %0,%1;" : "=f"(r) : "f"(x)); return r;
}

__global__ __launch_bounds__(NTHREADS, 2)
void bilateral_kernel(const float* __restrict__ in,
                      const float* __restrict__ prm,
                      float* __restrict__ out)
{
    extern __shared__ float smf[];
    // Quad-interleaved tile: ulonglong2 view [NQUAD][PLANE]; quad q holds ch 4q..4q+3
    ulonglong2* Tq  = (ulonglong2*)smf;
    float*      s2t = smf + CH * PLANE;     // [LH][LW], -1e30 marks OOB pixels

    const int tx  = threadIdx.x;         // 0..31
    const int ty  = threadIdx.y;         // 0..7
    const int tid = ty * TW + tx;
    const int bx0 = blockIdx.x * TW;
    const int by0 = blockIdx.y * TPH;
    const int b   = blockIdx.z;

    // Coefficients pre-scaled by log2(e) -> raw ex2
    float rcl[CH];
    #pragma unroll
    for (int c = 0; c < CH; c++) rcl[c] = __ldg(&prm[c]) * LOG2E;
    const float sxl = __ldg(&prm[CH]) * LOG2E;
    const float syl = __ldg(&prm[CH + 1]) * LOG2E;

    const float* inb = in + (size_t)b * CH * HH * WW;

    // ---- Phase 1: load haloed tile into quad-interleaved smem (zero-fill OOB) ----
    // Linear float index idx -> quad q = idx/(4*PLANE), p = (idx%(4*PLANE))>>2,
    // channel = 4q + (idx&3). Writes are sequential -> conflict-free STS.
    for (int idx = tid; idx < CH * PLANE; idx += NTHREADS) {
        int q    = idx / (4 * PLANE);
        int rem  = idx - q * (4 * PLANE);
        int p    = rem >> 2;
        int c    = 4 * q + (rem & 3);
        int lr = p / LW;
        int lc = p - lr * LW;
        int gy = by0 + lr - PAD;
        int gx = bx0 + lc - PAD;
        float v = 0.0f;
        if ((unsigned)gy < (unsigned)HH && (unsigned)gx < (unsigned)WW)
            v = __ldg(&inb[(size_t)c * HH * WW + (size_t)gy * WW + gx]);
        smf[idx] = v;
    }
    __syncthreads();

    // ---- Phase 2: s2'(q) = log2e * sum_c rc_c * x_c(q)^2 ; -1e30 where OOB ----
    for (int p = tid; p < PLANE; p += NTHREADS) {
        int lr = p / LW;
        int lc = p - lr * LW;
        int gy = by0 + lr - PAD;
        int gx = bx0 + lc - PAD;
        float s = -1e30f;
        if ((unsigned)gy < (unsigned)HH && (unsigned)gx < (unsigned)WW) {
            float a0 = 0.f, a1 = 0.f, a2 = 0.f, a3 = 0.f;
            #pragma unroll
            for (int q = 0; q < NQUAD; q++) {
                ulonglong2 v = Tq[q * PLANE + p];
                float x0, x1, x2, x3;
                upk2(v.x, x0, x1);
                upk2(v.y, x2, x3);
                a0 = fmaf(rcl[4*q + 0] * x0, x0, a0);
                a1 = fmaf(rcl[4*q + 1] * x1, x1, a1);
                a2 = fmaf(rcl[4*q + 2] * x2, x2, a2);
                a3 = fmaf(rcl[4*q + 3] * x3, x3, a3);
            }
            s = (a0 + a1) + (a2 + a3);
        }
        s2t[p] = s;
    }
    __syncthreads();

    // ---- Phase 3: three pixels per thread (rows lr0, lr0+2, lr0+4 share tap rows) ----
    // ty 0..7 -> lr0 = 6*(ty>>1) + (ty&1): triples {0,2,4},{1,3,5},{6,8,10},{7,9,11},...
    const int lr0 = 6 * (ty >> 1) + (ty & 1);
    const int cp0 = (lr0 + PAD) * LW + (tx + PAD);
    const int cp1 = cp0 + 2 * LW;
    const int cp2 = cp0 + 4 * LW;

    u64 rcn2[NPAIR];
    #pragma unroll
    for (int k = 0; k < NPAIR; k++)
        rcn2[k] = pk2(-2.0f * rcl[2*k], -2.0f * rcl[2*k + 1]);

    u64 y0p[NPAIR], y1p[NPAIR], y2p[NPAIR];
    #pragma unroll
    for (int q = 0; q < NQUAD; q++) {
        ulonglong2 v0 = Tq[q * PLANE + cp0];
        ulonglong2 v1 = Tq[q * PLANE + cp1];
        ulonglong2 v2 = Tq[q * PLANE + cp2];
        y0p[2*q]   = fmul2(rcn2[2*q],   v0.x);
        y0p[2*q+1] = fmul2(rcn2[2*q+1], v0.y);
        y1p[2*q]   = fmul2(rcn2[2*q],   v1.x);
        y1p[2*q+1] = fmul2(rcn2[2*q+1], v1.y);
        y2p[2*q]   = fmul2(rcn2[2*q],   v2.x);
        y2p[2*q+1] = fmul2(rcn2[2*q+1], v2.y);
    }
    const float s2p0 = s2t[cp0];
    const float s2p1 = s2t[cp1];
    const float s2p2 = s2t[cp2];

    float sxj[KS];
    #pragma unroll
    for (int j = 0; j < KS; j++) {
        float dxf = (float)((j - RAD) * DIL);
        sxj[j] = sxl * dxf * dxf;
    }

    float n00 = 0.f, n01 = 0.f, n02 = 0.f, d0 = 0.f;
    float n10 = 0.f, n11 = 0.f, n12 = 0.f, d1 = 0.f;
    float n20 = 0.f, n21 = 0.f, n22 = 0.f, d2 = 0.f;

    // Tap rows (padded coords): lr0 + 2*i, i = 0..8.
    // px0 valid i in [0,6] (dy0=2i-6); px1 valid [1,7] (dy1=2i-8); px2 valid [2,8] (dy2=2i-10).
    #pragma unroll 1
    for (int i = 0; i < 9; i++) {
        const float dy0 = (float)(2 * i - 6);
        const float dy1 = (float)(2 * i - 8);
        const float dy2 = (float)(2 * i - 10);
        float base0 = fmaf(syl * dy0, dy0, s2p0);
        float base1 = fmaf(syl * dy1, dy1, s2p1);
        float base2 = fmaf(syl * dy2, dy2, s2p2);
        if (i >= 7) base0 = -3e30f;              // rows invalid for px0 -> w=0
        if (i == 0 || i == 8) base1 = -3e30f;    // invalid for px1
        if (i <= 1) base2 = -3e30f;              // invalid for px2
        const int rowoff = (lr0 + 2 * i) * LW + tx;

        #pragma unroll
        for (int j = 0; j < KS; j++) {
            const int p = rowoff + 2 * j;
            const float t = s2t[p] + sxj[j];

            const ulonglong2 va = Tq[0 * PLANE + p];
            const ulonglong2 vb = Tq[1 * PLANE + p];
            const ulonglong2 vc = Tq[2 * PLANE + p];
            const ulonglong2 vd = Tq[3 * PLANE + p];

            // px0
            u64 A0 = fmul2(y0p[0], va.x);
            u64 A1 = fmul2(y0p[1], va.y);
            A0 = ffma2(y0p[2], vb.x, A0);
            A1 = ffma2(y0p[3], vb.y, A1);
            A0 = ffma2(y0p[4], vc.x, A0);
            A1 = ffma2(y0p[5], vc.y, A1);
            A0 = ffma2(y0p[6], vd.x, A0);
            A1 = ffma2(y0p[7], vd.y, A1);
            // px1
            u64 B0 = fmul2(y1p[0], va.x);
            u64 B1 = fmul2(y1p[1], va.y);
            B0 = ffma2(y1p[2], vb.x, B0);
            B1 = ffma2(y1p[3], vb.y, B1);
            B0 = ffma2(y1p[4], vc.x, B0);
            B1 = ffma2(y1p[5], vc.y, B1);
            B0 = ffma2(y1p[6], vd.x, B0);
            B1 = ffma2(y1p[7], vd.y, B1);
            // px2
            u64 C0 = fmul2(y2p[0], va.x);
            u64 C1 = fmul2(y2p[1], va.y);
            C0 = ffma2(y2p[2], vb.x, C0);
            C1 = ffma2(y2p[3], vb.y, C1);
            C0 = ffma2(y2p[4], vc.x, C0);
            C1 = ffma2(y2p[5], vc.y, C1);
            C0 = ffma2(y2p[6], vd.x, C0);
            C1 = ffma2(y2p[7], vd.y, C1);

            u64 SA = fadd2(A0, A1);
            u64 SB = fadd2(B0, B1);
            u64 SC = fadd2(C0, C1);
            float salo, sahi, sblo, sbhi, sclo, schi;
            upk2(SA, salo, sahi);
            upk2(SB, sblo, sbhi);
            upk2(SC, sclo, schi);

            const float w0 = ex2((salo + sahi) + (t + base0));
            const float w1 = ex2((sblo + sbhi) + (t + base1));
            const float w2 = ex2((sclo + schi) + (t + base2));

            float x0, x1, x2, x3dummy;
            upk2(va.x, x0, x1);
            upk2(va.y, x2, x3dummy);

            n00 = fmaf(w0, x0, n00);
            n01 = fmaf(w0, x1, n01);
            n02 = fmaf(w0, x2, n02);
            d0 += w0;
            n10 = fmaf(w1, x0, n10);
            n11 = fmaf(w1, x1, n11);
            n12 = fmaf(w1, x2, n12);
            d1 += w1;
            n20 = fmaf(w2, x0, n20);
            n21 = fmaf(w2, x1, n21);
            n22 = fmaf(w2, x2, n22);
            d2 += w2;
        }
    }

    const float inv0 = __fdividef(1.0f, d0);   // den >= 1 (center tap w=1)
    const float inv1 = __fdividef(1.0f, d1);
    const float inv2 = __fdividef(1.0f, d2);
    const int gy0 = by0 + lr0;
    const int gx  = bx0 + tx;
    const size_t CS = (size_t)HH * WW;
    const size_t ob = (size_t)b * DYN * CS + gx;
    if (gy0 < HH) {
        size_t o = ob + (size_t)gy0 * WW;
        out[o]          = n00 * inv0;
        out[o + CS]     = n01 * inv0;
        out[o + 2 * CS] = n02 * inv0;
    }
    if (gy0 + 2 < HH) {
        size_t o = ob + (size_t)(gy0 + 2) * WW;
        out[o]          = n10 * inv1;
        out[o + CS]     = n11 * inv1;
        out[o + 2 * CS] = n12 * inv1;
    }
    if (gy0 + 4 < HH) {
        size_t o = ob + (size_t)(gy0 + 4) * WW;
        out[o]          = n20 * inv2;
        out[o + CS]     = n21 * inv2;
        out[o + 2 * CS] = n22 * inv2;
    }
}

extern "C" void kernel_launch(void* const* d_in, const int* in_sizes, int n_in,
                              void* d_out, int out_size)
{
    const float* in  = (const float*)d_in[0];
    const float* prm = (const float*)d_in[1];
    float*       out = (float*)d_out;

    const int B = in_sizes[0] / (CH * HH * WW);   // = 4

    cudaFuncSetAttribute(bilateral_kernel,
                         cudaFuncAttributeMaxDynamicSharedMemorySize,
                         (int)SMEM_BYTES);

    dim3 block(TW, 8, 1);                              // 256 threads
    dim3 grid(WW / TW, (HH + TPH - 1) / TPH, B);       // 16 x 22 x 4
    bilateral_kernel<<<grid, block, SMEM_BYTES>>>(in, prm, out);
}